// round 7
// baseline (speedup 1.0000x reference)
#include <cuda_runtime.h>

#define NRAYS    16384
#define NSAMPLES 1024
#define EPS      0.05f
#define WARPS_PER_BLOCK 8
#define THREADS  (WARPS_PER_BLOCK * 32)
#define GRID     1024                      // 8192 warps x 2 rays = 16384 rays
#define WSTRIDE  8192                      // ray1 = ray0 + WSTRIDE

// ---------------- scratch (no allocation allowed) ----------------
__device__ double       g_empty_acc;
__device__ double       g_near_acc;
__device__ double       g_nmask_acc;
__device__ int          g_mask_kind;   // 0 = u8/bool, 1 = int32, 2 = float32
__device__ unsigned int g_done;        // block-completion ticket

// ---------------- init: zero accumulators + detect mask dtype ----------------
// Scans the first NRAYS bytes of the mask buffer (in-bounds for u8, i32 and
// f32 layouts) with uint4 loads. Classifies by which byte offsets (mod 4)
// ever hold nonzero:
//   u8 bool  : nonzeros at offset 1 (and others)
//   int32 0/1: nonzeros only at offset 0
//   f32 0/1  : 1.0f = 00 00 80 3F -> nonzeros at offsets 2/3 only
__global__ void init_detect_kernel(const uint4* __restrict__ mask_vec) {
    __shared__ int s_flags[8];
    const int tid  = threadIdx.x;
    const int warp = tid >> 5;

    int local = 0;
    #pragma unroll
    for (int k = 0; k < 4; k++) {
        const uint4 v = mask_vec[k * 256 + tid];
        const unsigned int w0 = v.x | v.y | v.z | v.w;  // OR keeps byte lanes
        if (w0 & 0x000000FFu) local |= 0x1;             // offset 0
        if (w0 & 0x0000FF00u) local |= 0x2;             // offset 1
        if (w0 & 0xFFFF0000u) local |= 0xC;             // offsets 2/3
    }
    local = __reduce_or_sync(0xFFFFFFFFu, local);
    if ((tid & 31) == 0) s_flags[warp] = local;
    __syncthreads();

    if (tid == 0) {
        int f = 0;
        #pragma unroll
        for (int i = 0; i < 8; i++) f |= s_flags[i];
        int kind;
        if      (f & 0x2) kind = 0;
        else if (f & 0xC) kind = 2;
        else if (f & 0x1) kind = 1;
        else              kind = 0;
        g_mask_kind = kind;
        g_empty_acc = 0.0;
        g_near_acc  = 0.0;
        g_nmask_acc = 0.0;
        g_done      = 0u;
    }
}

// ---------------- mask fetch per detected dtype ----------------
__device__ __forceinline__ float fetch_mask(const void* mask, int ray, int kind) {
    if (kind == 0)      return ((const unsigned char*)mask)[ray] ? 1.0f : 0.0f;
    else if (kind == 1) return ((const int*)mask)[ray]           ? 1.0f : 0.0f;
    else                return (((const float*)mask)[ray] != 0.0f) ? 1.0f : 0.0f;
}

// ---------------- main: two rays per warp, interleaved streams --------------
__global__ __launch_bounds__(THREADS) void loss_kernel(
    const float* __restrict__ ray_depth,
    const float* __restrict__ z_vals,
    const float* __restrict__ weights,
    const void*  __restrict__ mask,
    float*       __restrict__ out)
{
    const int warp  = threadIdx.x >> 5;
    const int lane  = threadIdx.x & 31;
    const int gwarp = blockIdx.x * WARPS_PER_BLOCK + warp;   // [0, 8192)
    const int ray0  = gwarp;
    const int ray1  = gwarp + WSTRIDE;

    const int  kind = g_mask_kind;
    const float m0 = fetch_mask(mask, ray0, kind);
    const float m1 = fetch_mask(mask, ray1, kind);

    const float d0  = __ldg(&ray_depth[ray0]);
    const float d1  = __ldg(&ray_depth[ray1]);
    const float lo0 = d0 - EPS, hi0 = d0 + EPS;
    const float lo1 = d1 - EPS, hi1 = d1 + EPS;

    const float4* __restrict__ zp0 = (const float4*)(z_vals  + (size_t)ray0 * NSAMPLES);
    const float4* __restrict__ wp0 = (const float4*)(weights + (size_t)ray0 * NSAMPLES);
    const float4* __restrict__ zp1 = (const float4*)(z_vals  + (size_t)ray1 * NSAMPLES);
    const float4* __restrict__ wp1 = (const float4*)(weights + (size_t)ray1 * NSAMPLES);

    float e0 = 0.0f, n0 = 0.0f;   // ray0: sum w^2 (empty), sum w (near)
    float e1 = 0.0f, n1 = 0.0f;   // ray1

    #pragma unroll
    for (int k = 0; k < NSAMPLES / (32 * 4); k++) {          // 8 iterations
        const int idx = k * 32 + lane;
        // 4 independent 128B loads per warp-iteration -> doubled MLP
        const float4 z0 = __ldcs(&zp0[idx]);
        const float4 w0 = __ldcs(&wp0[idx]);
        const float4 z1 = __ldcs(&zp1[idx]);
        const float4 w1 = __ldcs(&wp1[idx]);

        if (z0.x < lo0) e0 = fmaf(w0.x, w0.x, e0); else if (z0.x < hi0) n0 += w0.x;
        if (z0.y < lo0) e0 = fmaf(w0.y, w0.y, e0); else if (z0.y < hi0) n0 += w0.y;
        if (z0.z < lo0) e0 = fmaf(w0.z, w0.z, e0); else if (z0.z < hi0) n0 += w0.z;
        if (z0.w < lo0) e0 = fmaf(w0.w, w0.w, e0); else if (z0.w < hi0) n0 += w0.w;

        if (z1.x < lo1) e1 = fmaf(w1.x, w1.x, e1); else if (z1.x < hi1) n1 += w1.x;
        if (z1.y < lo1) e1 = fmaf(w1.y, w1.y, e1); else if (z1.y < hi1) n1 += w1.y;
        if (z1.z < lo1) e1 = fmaf(w1.z, w1.z, e1); else if (z1.z < hi1) n1 += w1.z;
        if (z1.w < lo1) e1 = fmaf(w1.w, w1.w, e1); else if (z1.w < hi1) n1 += w1.w;
    }

    // warp tree-reduce all four sums
    #pragma unroll
    for (int off = 16; off > 0; off >>= 1) {
        e0 += __shfl_xor_sync(0xFFFFFFFFu, e0, off);
        n0 += __shfl_xor_sync(0xFFFFFFFFu, n0, off);
        e1 += __shfl_xor_sync(0xFFFFFFFFu, e1, off);
        n1 += __shfl_xor_sync(0xFFFFFFFFu, n1, off);
    }

    // block reduce across 8 warps, then 3 atomics per block (1024 blocks)
    __shared__ float s_e[WARPS_PER_BLOCK], s_n[WARPS_PER_BLOCK], s_m[WARPS_PER_BLOCK];
    if (lane == 0) {
        const float dn0 = 1.0f - n0;
        const float dn1 = 1.0f - n1;
        s_e[warp] = e0 * m0 + e1 * m1;
        s_n[warp] = dn0 * dn0 * m0 + dn1 * dn1 * m1;
        s_m[warp] = m0 + m1;
    }
    __syncthreads();
    if (threadIdx.x == 0) {
        float E = 0.0f, N = 0.0f, M = 0.0f;
        #pragma unroll
        for (int i = 0; i < WARPS_PER_BLOCK; i++) { E += s_e[i]; N += s_n[i]; M += s_m[i]; }
        atomicAdd(&g_empty_acc, (double)E);
        atomicAdd(&g_near_acc,  (double)N);
        atomicAdd(&g_nmask_acc, (double)M);

        // last block finalizes the output (no separate kernel)
        __threadfence();
        const unsigned int ticket = atomicAdd(&g_done, 1u);
        if (ticket == (unsigned int)(GRID - 1)) {
            const double nm = g_nmask_acc;
            out[0] = (float)(g_empty_acc / nm);   // loss_empty
            out[1] = (float)(g_near_acc  / nm);   // loss_near
        }
    }
}

// ---------------- launch ----------------
extern "C" void kernel_launch(void* const* d_in, const int* in_sizes, int n_in,
                              void* d_out, int out_size) {
    const float* ray_depth = (const float*)d_in[0];   // [16384, 1]
    const float* z_vals    = (const float*)d_in[1];   // [16384, 1024] sorted
    const float* weights   = (const float*)d_in[2];   // [16384, 1024]
    const void*  ray_mask  = d_in[3];                 // [16384] bool/i32/f32

    init_detect_kernel<<<1, 256>>>((const uint4*)ray_mask);
    loss_kernel<<<GRID, THREADS>>>(ray_depth, z_vals, weights, ray_mask, (float*)d_out);
}